// round 1
// baseline (speedup 1.0000x reference)
#include <cuda_runtime.h>
#include <math.h>

#define B 32
#define C 128
#define NN 4096
#define HEADS 4
#define DH 32
#define HIDDEN 128
#define ROWS 384
#define QSCALE 0.17677669529663687f   /* 32^-0.5 */
#define GEPS 1e-5f

// ---------------- scratch (static __device__, no allocs) ----------------
__device__ float g_q[(size_t)B * HIDDEN * NN];     // softmaxed*scaled q
__device__ float g_k[(size_t)B * HIDDEN * NN];     // raw k projection
__device__ float g_v[(size_t)B * HIDDEN * NN];     // raw v projection
__device__ float g_ctx[B * HEADS * DH * DH];       // [b][h][d][e]
__device__ float g_M[B * HIDDEN * HIDDEN];         // folded Wo*blockdiag(ctx^T)
__device__ float g_y[(size_t)B * C * NN];          // pre-GroupNorm output
__device__ float g_sum[B];
__device__ float g_sumsq[B];

// ---------------- K0: zero the per-batch stats ----------------
__global__ void k0_zero() {
    int t = threadIdx.x;
    if (t < B) { g_sum[t] = 0.f; g_sumsq[t] = 0.f; }
}

// ---------------- K1: qkv projection + q softmax over d ----------------
// block = (ntile, b): computes rows 0..383 x cols nt*32..nt*32+31, K=128
// 256 threads: ct = tid&7 (4 cols each, contiguous), rt = tid>>3 (12 rows each)
__global__ void __launch_bounds__(256) k1_proj(
    const float* __restrict__ x,
    const float* __restrict__ Wq,
    const float* __restrict__ Wk,
    const float* __restrict__ Wv)
{
    __shared__ float sW[ROWS * 16];   // [r][kk], reused as sQ in epilogue
    __shared__ float sX[16 * 32];     // [kk][j]

    const int b  = blockIdx.y;
    const int n0 = blockIdx.x * 32;
    const int tid = threadIdx.x;
    const int ct = tid & 7;
    const int rt = tid >> 3;
    const int r0 = rt * 12;
    const int j0 = ct * 4;

    float4 acc[12];
#pragma unroll
    for (int i = 0; i < 12; i++) acc[i] = make_float4(0.f, 0.f, 0.f, 0.f);

    const float* xb = x + (size_t)b * C * NN;

    for (int kt = 0; kt < 8; kt++) {
        // load x tile: 16 rows x 32 cols = 128 float4, tid<128
        if (tid < 128) {
            int kk = tid >> 3, j4 = tid & 7;
            float4 t4 = *(const float4*)&xb[(size_t)(kt * 16 + kk) * NN + n0 + j4 * 4];
            *(float4*)&sX[kk * 32 + j4 * 4] = t4;
        }
        // load W tile: 384 rows x 16 cols = 1536 float4, 6 per thread
#pragma unroll
        for (int rr = 0; rr < 6; rr++) {
            int idx = tid + rr * 256;
            int r = idx >> 2, c4 = idx & 3;
            const float* Wp = (r < 128) ? Wq : ((r < 256) ? Wk : Wv);
            int rw = r & 127;
            float4 t4 = *(const float4*)&Wp[rw * 128 + kt * 16 + c4 * 4];
            *(float4*)&sW[r * 16 + c4 * 4] = t4;
        }
        __syncthreads();
#pragma unroll
        for (int kk = 0; kk < 16; kk++) {
            float4 xv = *(const float4*)&sX[kk * 32 + j0];
#pragma unroll
            for (int i = 0; i < 12; i++) {
                float w = sW[(r0 + i) * 16 + kk];
                acc[i].x += w * xv.x; acc[i].y += w * xv.y;
                acc[i].z += w * xv.z; acc[i].w += w * xv.w;
            }
        }
        __syncthreads();
    }

    // epilogue: q rows -> smem (softmax next); k,v -> global
    float* sQ = sW;   // 128*32 floats, fits in sW
#pragma unroll
    for (int i = 0; i < 12; i++) {
        int r = r0 + i;
        if (r < 128) {
            *(float4*)&sQ[r * 32 + j0] = acc[i];
        } else if (r < 256) {
            *(float4*)&g_k[((size_t)b * HIDDEN + (r - 128)) * NN + n0 + j0] = acc[i];
        } else {
            *(float4*)&g_v[((size_t)b * HIDDEN + (r - 256)) * NN + n0 + j0] = acc[i];
        }
    }
    __syncthreads();

    // q softmax over d (32 values per (h, col)), then * QSCALE
    if (tid < 128) {
        int h = tid >> 5, col = tid & 31;
        float mx = -1e30f;
#pragma unroll
        for (int d = 0; d < 32; d++) mx = fmaxf(mx, sQ[(h * 32 + d) * 32 + col]);
        float e[32];
        float s = 0.f;
#pragma unroll
        for (int d = 0; d < 32; d++) {
            e[d] = __expf(sQ[(h * 32 + d) * 32 + col] - mx);
            s += e[d];
        }
        float inv = QSCALE / s;
#pragma unroll
        for (int d = 0; d < 32; d++)
            g_q[((size_t)b * HIDDEN + h * 32 + d) * NN + n0 + col] = e[d] * inv;
    }
}

// ---------------- K2: k row-softmax stats + ctx = softmax(k) @ v^T ----------------
// one block per (b, h); 256 threads
__global__ void __launch_bounds__(256) k2_ctx()
{
    const int bh = blockIdx.x;
    const int b = bh >> 2, h = bh & 3;
    const float* kb = g_k + ((size_t)b * HIDDEN + h * 32) * NN;
    const float* vb = g_v + ((size_t)b * HIDDEN + h * 32) * NN;

    __shared__ float rmax[32], rsum[32];
    __shared__ float sK[32 * 128];        // exp'd k chunk [d][n]
    __shared__ float sVT[128 * 36];       // v chunk transposed [n][e], pad 36

    const int tid = threadIdx.x;
    const int w = tid >> 5, lane = tid & 31;

    // phase 1: per-row max then exp-sum (warp w handles rows w*4..w*4+3)
    for (int rr = 0; rr < 4; rr++) {
        int row = w * 4 + rr;
        const float4* kr4 = (const float4*)(kb + (size_t)row * NN);
        float4 mv = make_float4(-1e30f, -1e30f, -1e30f, -1e30f);
#pragma unroll 4
        for (int j = 0; j < 32; j++) {
            float4 t = kr4[lane + j * 32];
            mv.x = fmaxf(mv.x, t.x); mv.y = fmaxf(mv.y, t.y);
            mv.z = fmaxf(mv.z, t.z); mv.w = fmaxf(mv.w, t.w);
        }
        float mx = fmaxf(fmaxf(mv.x, mv.y), fmaxf(mv.z, mv.w));
#pragma unroll
        for (int o = 16; o; o >>= 1) mx = fmaxf(mx, __shfl_xor_sync(0xffffffffu, mx, o));
        float s = 0.f;
#pragma unroll 4
        for (int j = 0; j < 32; j++) {
            float4 t = kr4[lane + j * 32];
            s += __expf(t.x - mx) + __expf(t.y - mx) + __expf(t.z - mx) + __expf(t.w - mx);
        }
#pragma unroll
        for (int o = 16; o; o >>= 1) s += __shfl_xor_sync(0xffffffffu, s, o);
        if (lane == 0) { rmax[row] = mx; rsum[row] = s; }
    }
    __syncthreads();

    // phase 2: ctx[d][e] = sum_n exp(k[d][n]-mx_d) * v[e][n]
    const int d  = tid >> 3;
    const int e0 = (tid & 7) * 4;
    const int ld_row = tid >> 3;          // 0..31
    const int ld_c   = (tid & 7) * 16;    // 0..112
    float4 acc = make_float4(0.f, 0.f, 0.f, 0.f);

    for (int c0 = 0; c0 < NN; c0 += 128) {
        __syncthreads();
        {
            const float* kr = kb + (size_t)ld_row * NN + c0 + ld_c;
            float m = rmax[ld_row];
#pragma unroll
            for (int q4 = 0; q4 < 4; q4++) {
                float4 t = *(const float4*)(kr + q4 * 4);
                int base = ld_row * 128 + ld_c + q4 * 4;
                sK[base + 0] = __expf(t.x - m);
                sK[base + 1] = __expf(t.y - m);
                sK[base + 2] = __expf(t.z - m);
                sK[base + 3] = __expf(t.w - m);
            }
            const float* vr = vb + (size_t)ld_row * NN + c0 + ld_c;
#pragma unroll
            for (int q4 = 0; q4 < 4; q4++) {
                float4 t = *(const float4*)(vr + q4 * 4);
                int nc = ld_c + q4 * 4;
                sVT[(nc + 0) * 36 + ld_row] = t.x;
                sVT[(nc + 1) * 36 + ld_row] = t.y;
                sVT[(nc + 2) * 36 + ld_row] = t.z;
                sVT[(nc + 3) * 36 + ld_row] = t.w;
            }
        }
        __syncthreads();
#pragma unroll 4
        for (int n = 0; n < 128; n++) {
            float kd = sK[d * 128 + n];
            float4 vv = *(const float4*)&sVT[n * 36 + e0];
            acc.x += kd * vv.x; acc.y += kd * vv.y;
            acc.z += kd * vv.z; acc.w += kd * vv.w;
        }
    }
    float inv = 1.0f / rsum[d];
    acc.x *= inv; acc.y *= inv; acc.z *= inv; acc.w *= inv;
    *(float4*)&g_ctx[((size_t)bh * 32 + d) * 32 + e0] = acc;
}

// ---------------- K3: fold M_b = Wo @ blockdiag(ctx^T) ----------------
// one block per b; 256 threads; thread: o = tid>>1, half = tid&1 (64 hd each)
__global__ void __launch_bounds__(256) k3_fold(const float* __restrict__ Wo)
{
    const int b = blockIdx.x;
    __shared__ float sctx[HEADS * DH * DH];   // 4096 floats
    const int tid = threadIdx.x;
#pragma unroll
    for (int rr = 0; rr < 4; rr++) {
        int idx = tid + rr * 256;   // 1024 float4 total
        *(float4*)&sctx[idx * 4] = *(const float4*)&g_ctx[(size_t)b * 4096 + idx * 4];
    }
    __syncthreads();

    const int o = tid >> 1;
    const int half = tid & 1;
    float* Mout = g_M + (size_t)b * HIDDEN * HIDDEN + o * HIDDEN;

#pragma unroll
    for (int hh = 0; hh < 2; hh++) {
        int h = half * 2 + hh;
        float wo[32];
#pragma unroll
        for (int q4 = 0; q4 < 8; q4++) {
            float4 t = *(const float4*)&Wo[o * 128 + h * 32 + q4 * 4];
            wo[q4 * 4 + 0] = t.x; wo[q4 * 4 + 1] = t.y;
            wo[q4 * 4 + 2] = t.z; wo[q4 * 4 + 3] = t.w;
        }
        for (int dd = 0; dd < 32; dd++) {
            float s = 0.f;
#pragma unroll
            for (int q4 = 0; q4 < 8; q4++) {
                float4 cv = *(const float4*)&sctx[(h * 32 + dd) * 32 + q4 * 4];
                s += wo[q4 * 4 + 0] * cv.x + wo[q4 * 4 + 1] * cv.y
                   + wo[q4 * 4 + 2] * cv.z + wo[q4 * 4 + 3] * cv.w;
            }
            // M[o][h*32+dd] = sum_e Wo[o][h*32+e] * ctx[h][dd][e]
            Mout[h * 32 + dd] = s;
        }
    }
}

// ---------------- K4: y = M_b @ q + bo, + per-batch sum/sumsq ----------------
// block = (ntile, b): rows 128 x cols 32, K=128
__global__ void __launch_bounds__(256) k4_out(const float* __restrict__ bo)
{
    __shared__ float sM[128 * 16];
    __shared__ float sQ2[16 * 32];
    __shared__ float redS[8], redQ[8];

    const int b  = blockIdx.y;
    const int n0 = blockIdx.x * 32;
    const int tid = threadIdx.x;
    const int ct = tid & 7;
    const int rt = tid >> 3;
    const int r0 = rt * 4;
    const int j0 = ct * 4;

    float4 acc[4];
#pragma unroll
    for (int i = 0; i < 4; i++) acc[i] = make_float4(0.f, 0.f, 0.f, 0.f);

    const float* Mb = g_M + (size_t)b * HIDDEN * HIDDEN;
    const float* qb = g_q + (size_t)b * HIDDEN * NN;

    for (int kt = 0; kt < 8; kt++) {
        if (tid < 128) {
            int kk = tid >> 3, j4 = tid & 7;
            *(float4*)&sQ2[kk * 32 + j4 * 4] =
                *(const float4*)&qb[(size_t)(kt * 16 + kk) * NN + n0 + j4 * 4];
        }
#pragma unroll
        for (int rr = 0; rr < 2; rr++) {
            int idx = tid + rr * 256;   // 512 float4
            int r = idx >> 2, c4 = idx & 3;
            *(float4*)&sM[r * 16 + c4 * 4] =
                *(const float4*)&Mb[r * 128 + kt * 16 + c4 * 4];
        }
        __syncthreads();
#pragma unroll
        for (int kk = 0; kk < 16; kk++) {
            float4 xv = *(const float4*)&sQ2[kk * 32 + j0];
#pragma unroll
            for (int i = 0; i < 4; i++) {
                float w = sM[(r0 + i) * 16 + kk];
                acc[i].x += w * xv.x; acc[i].y += w * xv.y;
                acc[i].z += w * xv.z; acc[i].w += w * xv.w;
            }
        }
        __syncthreads();
    }

    float lsum = 0.f, lsq = 0.f;
#pragma unroll
    for (int i = 0; i < 4; i++) {
        int r = r0 + i;
        float bb = bo[r];
        acc[i].x += bb; acc[i].y += bb; acc[i].z += bb; acc[i].w += bb;
        *(float4*)&g_y[((size_t)b * C + r) * NN + n0 + j0] = acc[i];
        lsum += acc[i].x + acc[i].y + acc[i].z + acc[i].w;
        lsq  += acc[i].x * acc[i].x + acc[i].y * acc[i].y
              + acc[i].z * acc[i].z + acc[i].w * acc[i].w;
    }
    const int w = tid >> 5, lane = tid & 31;
#pragma unroll
    for (int o = 16; o; o >>= 1) {
        lsum += __shfl_xor_sync(0xffffffffu, lsum, o);
        lsq  += __shfl_xor_sync(0xffffffffu, lsq,  o);
    }
    if (lane == 0) { redS[w] = lsum; redQ[w] = lsq; }
    __syncthreads();
    if (tid == 0) {
        float s = 0.f, q = 0.f;
#pragma unroll
        for (int i = 0; i < 8; i++) { s += redS[i]; q += redQ[i]; }
        atomicAdd(&g_sum[b], s);
        atomicAdd(&g_sumsq[b], q);
    }
}

// ---------------- K5: GroupNorm(1 group) ----------------
__global__ void __launch_bounds__(256) k5_norm(
    const float* __restrict__ gn_w, const float* __restrict__ gn_b,
    float* __restrict__ out)
{
    size_t i = (size_t)blockIdx.x * blockDim.x + threadIdx.x;
    if (i >= (size_t)B * C * NN) return;
    int b = (int)(i / ((size_t)C * NN));
    int c = (int)((i / NN) & (C - 1));
    const float cn = (float)(C * NN);
    float mu = g_sum[b] / cn;
    float var = g_sumsq[b] / cn - mu * mu;
    float is = rsqrtf(var + GEPS);
    out[i] = (g_y[i] - mu) * is * gn_w[c] + gn_b[c];
}

// ---------------- launch ----------------
extern "C" void kernel_launch(void* const* d_in, const int* in_sizes, int n_in,
                              void* d_out, int out_size)
{
    const float* x  = (const float*)d_in[0];
    const float* Wq = (const float*)d_in[1];
    const float* Wk = (const float*)d_in[2];
    const float* Wv = (const float*)d_in[3];
    const float* Wo = (const float*)d_in[4];
    const float* bo = (const float*)d_in[5];
    const float* gw = (const float*)d_in[6];
    const float* gb = (const float*)d_in[7];
    float* out = (float*)d_out;

    k0_zero<<<1, 32>>>();
    k1_proj<<<dim3(128, 32), 256>>>(x, Wq, Wk, Wv);
    k2_ctx<<<128, 256>>>();
    k3_fold<<<32, 256>>>(Wo);
    k4_out<<<dim3(128, 32), 256>>>(bo);
    int total = B * C * NN;
    k5_norm<<<(total + 255) / 256, 256>>>(gw, gb, out);
}